// round 4
// baseline (speedup 1.0000x reference)
#include <cuda_runtime.h>

#define D_MODEL   2048
#define EXP       4           // E
#define NTHREADS  256
#define NWARPS    (NTHREADS / 32)
#define F4_ROW    (D_MODEL / 4)            // 512 float4 per row
#define VEC_ITERS (F4_ROW / NTHREADS)      // 2
#define EPS       1e-5f

// out[b,t,d] = residual * (sum(static_beta) + E*dyn_beta)
//            + x        * (sum_{e,j>=1} static_alpha[e,j] + E*sum_{j>=1} dyn_alpha[j])
// dyn_alpha[j] = tanh(inv * dot(x*w, A[:,j])) * a_scale
// dyn_beta     = tanh(inv * dot(x*w, Bfn))    * b_scale
// inv = rsqrt(mean(x^2) + eps)

__global__ __launch_bounds__(NTHREADS)
void hyperconn_kernel(const float* __restrict__ x,
                      const float* __restrict__ residual,
                      const float* __restrict__ w,
                      const float* __restrict__ salpha,   // [E, E+1]
                      const float* __restrict__ sbeta,    // [E]
                      const float* __restrict__ afn,      // [D, E+1]
                      const float* __restrict__ ascale,   // [1]
                      const float* __restrict__ bfn,      // [D]
                      const float* __restrict__ bscale,   // [1]
                      float* __restrict__ out,
                      int nrows)
{
    // Transposed weight layout for conflict-free LDS.128:
    // For float4-group f (covers d = 4f..4f+3) and in-group element k,
    //   sAT[k*F4_ROW + f] = { w[d]*A[d][1], w[d]*A[d][2], w[d]*A[d][3], w[d]*A[d][4] }, d = 4f+k
    //   sB4[f]            = { w[4f+c]*bfn[4f+c] } c=0..3
    __shared__ float4 sAT[4 * F4_ROW];   // 32 KB
    __shared__ float4 sB4[F4_ROW];       // 8 KB
    __shared__ float  red[NWARPS][6];
    __shared__ float  bc[2];
    __shared__ float  sbase[2];

    const int tid  = threadIdx.x;
    const int lane = tid & 31;
    const int warp = tid >> 5;

    // ---- Stage weights into smem (once per persistent CTA) ----
    for (int d = tid; d < D_MODEL; d += NTHREADS) {
        float wd = w[d];
        const float* a = afn + d * (EXP + 1);
        int f = d >> 2, k = d & 3;
        sAT[k * F4_ROW + f] = make_float4(wd * a[1], wd * a[2], wd * a[3], wd * a[4]);
        ((float*)sB4)[d] = wd * bfn[d];   // sB4[f] element c == index d
    }
    if (tid == 0) {
        float cb = 0.f, bb = 0.f;
        for (int e = 0; e < EXP; e++) {
            bb += sbeta[e];
            for (int j = 1; j <= EXP; j++) cb += salpha[e * (EXP + 1) + j];
        }
        sbase[0] = cb;
        sbase[1] = bb;
    }
    __syncthreads();

    const float a_s = ascale[0];
    const float b_s = bscale[0];
    const float csum_base = sbase[0];
    const float bsum_base = sbase[1];

    for (int row = blockIdx.x; row < nrows; row += gridDim.x) {
        const float4* xr = (const float4*)(x        + (size_t)row * D_MODEL);
        const float4* rr = (const float4*)(residual + (size_t)row * D_MODEL);
        float4*       orow = (float4*)(out + (size_t)row * D_MODEL);

        float4 xv[VEC_ITERS], rv[VEC_ITERS];
        float ss = 0.f, r1 = 0.f, r2 = 0.f, r3 = 0.f, r4 = 0.f, rb = 0.f;

        #pragma unroll
        for (int i = 0; i < VEC_ITERS; i++) {
            int f = tid + i * NTHREADS;          // lane-contiguous float4 index
            float4 xx = xr[f];
            float4 rq = rr[f];
            xv[i] = xx; rv[i] = rq;

            float4 bb = sB4[f];
            ss += xx.x * xx.x + xx.y * xx.y + xx.z * xx.z + xx.w * xx.w;
            rb += xx.x * bb.x + xx.y * bb.y + xx.z * bb.z + xx.w * bb.w;

            const float xe[4] = { xx.x, xx.y, xx.z, xx.w };
            #pragma unroll
            for (int k = 0; k < 4; k++) {
                float4 a = sAT[k * F4_ROW + f];  // conflict-free: consecutive 16B per lane
                float xd = xe[k];
                r1 += xd * a.x; r2 += xd * a.y; r3 += xd * a.z; r4 += xd * a.w;
            }
        }

        // ---- warp reduce 6 values ----
        #pragma unroll
        for (int off = 16; off > 0; off >>= 1) {
            ss += __shfl_xor_sync(0xffffffffu, ss, off);
            r1 += __shfl_xor_sync(0xffffffffu, r1, off);
            r2 += __shfl_xor_sync(0xffffffffu, r2, off);
            r3 += __shfl_xor_sync(0xffffffffu, r3, off);
            r4 += __shfl_xor_sync(0xffffffffu, r4, off);
            rb += __shfl_xor_sync(0xffffffffu, rb, off);
        }
        if (lane == 0) {
            red[warp][0] = ss; red[warp][1] = r1; red[warp][2] = r2;
            red[warp][3] = r3; red[warp][4] = r4; red[warp][5] = rb;
        }
        __syncthreads();

        if (tid == 0) {
            float t0 = 0, t1 = 0, t2 = 0, t3 = 0, t4 = 0, t5 = 0;
            #pragma unroll
            for (int q = 0; q < NWARPS; q++) {
                t0 += red[q][0]; t1 += red[q][1]; t2 += red[q][2];
                t3 += red[q][3]; t4 += red[q][4]; t5 += red[q][5];
            }
            float inv  = rsqrtf(t0 * (1.0f / D_MODEL) + EPS);
            float da   = tanhf(t1 * inv) + tanhf(t2 * inv)
                       + tanhf(t3 * inv) + tanhf(t4 * inv);
            float csum = csum_base + (float)EXP * a_s * da;
            float db   = tanhf(t5 * inv) * b_s;
            float bsum = bsum_base + (float)EXP * db;
            bc[0] = csum; bc[1] = bsum;
        }
        __syncthreads();

        const float csum = bc[0], bsum = bc[1];
        #pragma unroll
        for (int i = 0; i < VEC_ITERS; i++) {
            int f = tid + i * NTHREADS;
            float4 xx = xv[i], rq = rv[i], o;
            o.x = rq.x * bsum + xx.x * csum;
            o.y = rq.y * bsum + xx.y * csum;
            o.z = rq.z * bsum + xx.z * csum;
            o.w = rq.w * bsum + xx.w * csum;
            orow[f] = o;
        }
    }
}

extern "C" void kernel_launch(void* const* d_in, const int* in_sizes, int n_in,
                              void* d_out, int out_size)
{
    const float* x        = (const float*)d_in[0];
    const float* residual = (const float*)d_in[1];
    const float* w        = (const float*)d_in[2];
    const float* salpha   = (const float*)d_in[3];
    const float* sbeta    = (const float*)d_in[4];
    const float* afn      = (const float*)d_in[5];
    const float* ascale   = (const float*)d_in[6];
    const float* bfn      = (const float*)d_in[7];
    const float* bscale   = (const float*)d_in[8];
    float* out = (float*)d_out;

    int nrows = in_sizes[0] / D_MODEL;   // B*T = 16384

    // Persistent grid: 5 CTAs/SM (40.3KB static smem each) x 148 SMs
    int grid = 148 * 5;
    if (grid > nrows) grid = nrows;

    hyperconn_kernel<<<grid, NTHREADS>>>(x, residual, w, salpha, sbeta,
                                         afn, ascale, bfn, bscale, out, nrows);
}